// round 10
// baseline (speedup 1.0000x reference)
#include <cuda_runtime.h>
#include <cstdint>
#include <cstddef>

#define BATCH 64
#define SEQT  512
#define DIN   256
#define HDIM  1024
#define DOUT  128
#define GRID  128

typedef unsigned long long u64;

// ---------------- scratch (device globals: allocation-free) ----------------
__device__ __align__(16) static float g_P[(size_t)BATCH * SEQT * HDIM]; // pre-activations
__device__ __align__(16) static float g_S[(size_t)BATCH * SEQT * HDIM]; // layer outputs / h
__device__ volatile unsigned g_flags[GRID];                             // per-CTA progress flags

// ---------------- packed f32x2 helpers ----------------
__device__ __forceinline__ void fma2(u64 &d, u64 a, u64 b) {
    asm("fma.rn.f32x2 %0, %1, %2, %0;" : "+l"(d) : "l"(a), "l"(b));
}
__device__ __forceinline__ u64 add2(u64 a, u64 b) {
    u64 r; asm("add.rn.f32x2 %0, %1, %2;" : "=l"(r) : "l"(a), "l"(b)); return r;
}
__device__ __forceinline__ float2 up2(u64 v) {
    float2 f; asm("mov.b64 {%0, %1}, %2;" : "=f"(f.x), "=f"(f.y) : "l"(v)); return f;
}

__device__ __forceinline__ uint32_t smem_u32(const void* p) {
    uint32_t a;
    asm("{ .reg .u64 t; cvta.to.shared.u64 t, %1; cvt.u32.u64 %0, t; }" : "=r"(a) : "l"(p));
    return a;
}
__device__ __forceinline__ void cpasync16(uint32_t dst, const void* src) {
    asm volatile("cp.async.cg.shared.global [%0], [%1], 16;" :: "r"(dst), "l"(src));
}
__device__ __forceinline__ void cpasync_commit_wait() {
    asm volatile("cp.async.commit_group;");
    asm volatile("cp.async.wait_group 0;" ::: "memory");
}

// ============================================================================
// Projection GEMM: C[32768][1024] = A[32768][K] @ W[1024][K]^T + (bi + bh)
// ============================================================================
__global__ void __launch_bounds__(256, 2) proj_kernel(
    const float* __restrict__ A, const float* __restrict__ W,
    const float* __restrict__ bi, const float* __restrict__ bh,
    float* __restrict__ C, int K)
{
    __shared__ __align__(16) float sA[16 * 132];
    __shared__ __align__(16) float sB[16 * 132];

    const int tid = threadIdx.x;
    const int tm = blockIdx.x >> 3;
    const int tn = blockIdx.x & 7;
    const int ty = tid >> 4;
    const int tx = tid & 15;
    const int lr = tid >> 2;
    const int lq = tid & 3;

    u64 acc[8][4];
    #pragma unroll
    for (int i = 0; i < 8; i++)
        #pragma unroll
        for (int j = 0; j < 4; j++) acc[i][j] = 0ull;

    const float* Ab = A + (size_t)(tm * 128) * K;
    const float* Wb = W + (size_t)(tn * 128) * K;

    for (int kc = 0; kc < K; kc += 16) {
        __syncthreads();
        #pragma unroll
        for (int p = 0; p < 2; p++) {
            const int rr = lr + p * 64;
            const float4 a4 = __ldg((const float4*)(Ab + (size_t)rr * K + kc + lq * 4));
            const float4 w4 = __ldg((const float4*)(Wb + (size_t)rr * K + kc + lq * 4));
            sA[(lq * 4 + 0) * 132 + rr] = a4.x;
            sA[(lq * 4 + 1) * 132 + rr] = a4.y;
            sA[(lq * 4 + 2) * 132 + rr] = a4.z;
            sA[(lq * 4 + 3) * 132 + rr] = a4.w;
            sB[(lq * 4 + 0) * 132 + rr] = w4.x;
            sB[(lq * 4 + 1) * 132 + rr] = w4.y;
            sB[(lq * 4 + 2) * 132 + rr] = w4.z;
            sB[(lq * 4 + 3) * 132 + rr] = w4.w;
        }
        __syncthreads();
        #pragma unroll
        for (int kk = 0; kk < 16; kk++) {
            const float4 a0 = *(const float4*)&sA[kk * 132 + ty * 4];
            const float4 a1 = *(const float4*)&sA[kk * 132 + 64 + ty * 4];
            const ulonglong2 bq0 = *(const ulonglong2*)&sB[kk * 132 + tx * 4];
            const ulonglong2 bq1 = *(const ulonglong2*)&sB[kk * 132 + 64 + tx * 4];
            const float am[8] = {a0.x, a0.y, a0.z, a0.w, a1.x, a1.y, a1.z, a1.w};
            #pragma unroll
            for (int i = 0; i < 8; i++) {
                u64 ad;
                asm("mov.b64 %0, {%1, %1};" : "=l"(ad) : "f"(am[i]));
                fma2(acc[i][0], ad, bq0.x);
                fma2(acc[i][1], ad, bq0.y);
                fma2(acc[i][2], ad, bq1.x);
                fma2(acc[i][3], ad, bq1.y);
            }
        }
    }

    const int n0 = tn * 128 + tx * 4;
    const int n1 = n0 + 64;
    float4 bia0, bia1;
    {
        const float4 i0 = __ldg((const float4*)(bi + n0));
        const float4 h0 = __ldg((const float4*)(bh + n0));
        const float4 i1 = __ldg((const float4*)(bi + n1));
        const float4 h1 = __ldg((const float4*)(bh + n1));
        bia0 = make_float4(i0.x + h0.x, i0.y + h0.y, i0.z + h0.z, i0.w + h0.w);
        bia1 = make_float4(i1.x + h1.x, i1.y + h1.y, i1.z + h1.z, i1.w + h1.w);
    }
    #pragma unroll
    for (int i = 0; i < 8; i++) {
        const int m = tm * 128 + (i < 4 ? ty * 4 + i : 64 + ty * 4 + (i - 4));
        const float2 c0 = up2(acc[i][0]), c1 = up2(acc[i][1]);
        const float2 c2 = up2(acc[i][2]), c3 = up2(acc[i][3]);
        *(float4*)(C + (size_t)m * HDIM + n0) =
            make_float4(c0.x + bia0.x, c0.y + bia0.y, c1.x + bia0.z, c1.y + bia0.w);
        *(float4*)(C + (size_t)m * HDIM + n1) =
            make_float4(c2.x + bia1.x, c2.y + bia1.y, c3.x + bia1.z, c3.y + bia1.w);
    }
}

// ============================================================================
// Recurrent scan — ASYNC DATAFLOW version (no global barrier).
// 128 CTAs x 256 thr (8 warps), 1 CTA/SM, CTA tile [16b x 32o].
// Register-resident weights (R5 core). S is written per-t (no overwrite), so
// the only ordering needed is per-producer flags: CTA sets flag=t after its
// h_t is stored; consumers poll only the 32 peers of their batch group.
// Each warp handles 4 peers: poll flag -> cp.async that peer's 128B x 16row
// block. Staging overlaps inter-CTA skew. Double-buffered smem h (t parity).
// ============================================================================
#define SM_H0  0                          // hbuf[2][16][1024] floats
#define SM_R   (2 * 16 * 1024)            // red: u64[8][512]
#define SCAN_SMEM_BYTES ((SM_R) * 4 + 8 * 512 * 8)   // 163,840 B

__global__ void __launch_bounds__(256, 1) scan_kernel(
    const float* __restrict__ P, float* __restrict__ S,
    const float* __restrict__ Whh)
{
    extern __shared__ __align__(16) float sm[];
    float* hB[2] = { sm + SM_H0, sm + SM_H0 + 16 * 1024 };
    u64*   red = (u64*)(sm + SM_R);

    const int tid  = threadIdx.x;
    const int cta  = blockIdx.x;
    const int gbase = cta & ~31;        // peer group base (batch group)
    const int b0 = (cta >> 5) * 16;     // batch block
    const int o0 = (cta & 31) * 32;     // output block
    const int warp = tid >> 5;          // k-range owner: [warp*128, +128)
    const int lane = tid & 31;          // output owner: o0 + lane
    const int kb = warp * 128;

    // ---- load this lane's weight slice into registers (once per layer) ----
    u64 wreg[64];
    {
        const float* wrow = Whh + (size_t)(o0 + lane) * HDIM + kb;
        #pragma unroll
        for (int c = 0; c < 32; c++) {
            const float4 w4 = __ldg((const float4*)(wrow + c * 4));
            wreg[2 * c]     = ((const u64*)&w4)[0];
            wreg[2 * c + 1] = ((const u64*)&w4)[1];
        }
    }

    const unsigned base = g_flags[cta];   // equal across CTAs at launch

    // Epilogue mapping: 2 adjacent outputs per thread
    const int pb = tid >> 4;
    const int po = (tid & 15) * 2;
    const size_t prow = ((size_t)(b0 + pb) * SEQT) * HDIM + o0 + po;

    // t = 0: h = relu(pre); publish
    {
        const float2 p2 = *(const float2*)(P + prow);
        *(float2*)(S + prow) = make_float2(fmaxf(p2.x, 0.f), fmaxf(p2.y, 0.f));
    }
    __syncthreads();
    if (tid == 0) { __threadfence(); g_flags[cta] = base + 1; }

    const float* Sg = S + (size_t)b0 * SEQT * HDIM;   // this group's batch rows

    for (int t = 1; t < SEQT; t++) {
        const float2 p2 = __ldg((const float2*)(P + prow + (size_t)t * HDIM));

        float* hb = hB[(t - 1) & 1];
        const uint32_t hb_a = smem_u32(hb);

        // ---- per-peer dataflow staging: warp w handles peers w*4..w*4+3 ----
        {
            const size_t tprev = (size_t)(t - 1) * HDIM;
            #pragma unroll
            for (int jj = 0; jj < 4; jj++) {
                const int j = warp * 4 + jj;        // peer o-block index
                if (lane == 0) {
                    while (g_flags[gbase + j] < base + (unsigned)t) { }
                }
                __syncwarp();
                // peer j produced h[b0..b0+16)[32j..32j+32): 16 rows x 128B
                #pragma unroll
                for (int r = 0; r < 4; r++) {
                    const int idx = r * 32 + lane;        // 0..127
                    const int bb = idx >> 3;              // 0..15
                    const int q  = idx & 7;               // 0..7 (16B quads)
                    cpasync16(hb_a + (uint32_t)(bb * 1024 + j * 32 + q * 4) * 4,
                              Sg + (size_t)bb * SEQT * HDIM + tprev + j * 32 + q * 4);
                }
            }
            cpasync_commit_wait();
        }
        __syncthreads();

        // ---- compute: per lane, 16 batches x 1 output x 128 k (R5 core) ----
        u64 accF[16];
        #pragma unroll
        for (int b = 0; b < 16; b++) {
            const ulonglong2* hrow = (const ulonglong2*)&hb[b * 1024 + kb];
            u64 a0 = 0ull, a1 = 0ull;
            #pragma unroll
            for (int c = 0; c < 32; c++) {
                const ulonglong2 hp = hrow[c];   // broadcast across warp
                fma2(a0, hp.x, wreg[2 * c]);
                fma2(a1, hp.y, wreg[2 * c + 1]);
            }
            accF[b] = add2(a0, a1);
        }

        // stash warp partials: red[warp][b][lane]
        #pragma unroll
        for (int b = 0; b < 16; b++)
            red[warp * 512 + b * 32 + lane] = accF[b];
        __syncthreads();

        // final reduce over 8 warps, fold (even,odd) halves, relu, store h_t
        {
            ulonglong2 v = *(const ulonglong2*)&red[pb * 32 + po];
            u64 s0 = v.x, s1 = v.y;
            #pragma unroll
            for (int w8 = 1; w8 < 8; w8++) {
                const ulonglong2 r = *(const ulonglong2*)&red[w8 * 512 + pb * 32 + po];
                s0 = add2(s0, r.x);
                s1 = add2(s1, r.y);
            }
            const float2 a0 = up2(s0), a1 = up2(s1);
            *(float2*)(S + prow + (size_t)t * HDIM) =
                make_float2(fmaxf(a0.x + a0.y + p2.x, 0.f),
                            fmaxf(a1.x + a1.y + p2.y, 0.f));
        }
        __syncthreads();
        if (tid == 0) { __threadfence(); g_flags[cta] = base + (unsigned)t + 1; }
    }
}

// ============================================================================
// FC: out[64][128] = S[:, T-1, :] @ fc_w^T + fc_b
// ============================================================================
__global__ void __launch_bounds__(128) fc_kernel(
    const float* __restrict__ S, const float* __restrict__ fw,
    const float* __restrict__ fb, float* __restrict__ out)
{
    __shared__ __align__(16) float sx[HDIM];
    const int b = blockIdx.x, tid = threadIdx.x;
    const float* xrow = S + ((size_t)b * SEQT + (SEQT - 1)) * HDIM;
    for (int i = tid; i < HDIM / 4; i += 128)
        *(float4*)&sx[i * 4] = __ldcg((const float4*)(xrow + i * 4));
    __syncthreads();
    float acc = 0.f;
    const float* wrow = fw + (size_t)tid * HDIM;
    #pragma unroll 8
    for (int q = 0; q < HDIM / 4; q++) {
        const float4 w4 = __ldg((const float4*)(wrow + q * 4));
        const float4 x4 = *(const float4*)&sx[q * 4];
        acc += w4.x * x4.x + w4.y * x4.y + w4.z * x4.z + w4.w * x4.w;
    }
    out[(size_t)b * DOUT + tid] = acc + __ldg(fb + tid);
}

// ============================================================================
extern "C" void kernel_launch(void* const* d_in, const int* in_sizes, int n_in,
                              void* d_out, int out_size)
{
    const float* x    = (const float*)d_in[0];   // [64,512,256]
    const float* wih0 = (const float*)d_in[1];   // [1024,256]
    const float* wihr = (const float*)d_in[2];   // [2,1024,1024]
    const float* whh  = (const float*)d_in[3];   // [3,1024,1024]
    const float* bih  = (const float*)d_in[4];   // [3,1024]
    const float* bhh  = (const float*)d_in[5];   // [3,1024]
    const float* fcw  = (const float*)d_in[6];   // [128,1024]
    const float* fcb  = (const float*)d_in[7];   // [128]
    float* out = (float*)d_out;                  // [64,128]

    cudaFuncSetAttribute(scan_kernel, cudaFuncAttributeMaxDynamicSharedMemorySize,
                         SCAN_SMEM_BYTES);

    void *pP = nullptr, *pS = nullptr;
    cudaGetSymbolAddress(&pP, g_P);
    cudaGetSymbolAddress(&pS, g_S);
    float* P  = (float*)pP;
    float* Sq = (float*)pS;

    proj_kernel<<<2048, 256>>>(x, wih0, bih, bhh, P, DIN);
    scan_kernel<<<GRID, 256, SCAN_SMEM_BYTES>>>(P, Sq, whh);
    proj_kernel<<<2048, 256>>>(Sq, wihr, bih + HDIM, bhh + HDIM, P, HDIM);
    scan_kernel<<<GRID, 256, SCAN_SMEM_BYTES>>>(P, Sq, whh + (size_t)HDIM * HDIM);
    proj_kernel<<<2048, 256>>>(Sq, wihr + (size_t)HDIM * HDIM, bih + 2 * HDIM, bhh + 2 * HDIM, P, HDIM);
    scan_kernel<<<GRID, 256, SCAN_SMEM_BYTES>>>(P, Sq, whh + 2 * (size_t)HDIM * HDIM);
    fc_kernel<<<BATCH, 128>>>(Sq, fcw, fcb, out);
}

// round 11
// speedup vs baseline: 2.6424x; 2.6424x over previous
#include <cuda_runtime.h>
#include <cuda_bf16.h>
#include <cstdint>
#include <cstddef>

#define BATCH 64
#define SEQT  512
#define DIN   256
#define HDIM  1024
#define DOUT  128
#define GRID  128

typedef unsigned long long u64;

// ---------------- scratch (device globals: allocation-free) ----------------
__device__ __align__(16) static float g_P[(size_t)BATCH * SEQT * HDIM]; // pre-activations
__device__ __align__(16) static float g_S[(size_t)BATCH * SEQT * HDIM]; // layer outputs / h
__device__ __align__(16) static __nv_bfloat16 g_Hhi[2][BATCH * HDIM];   // h hi plane (t parity)
__device__ __align__(16) static __nv_bfloat16 g_Hlo[2][BATCH * HDIM];   // h lo plane
__device__ volatile unsigned g_flags[GRID];                             // barrier flags

// ---------------- packed f32x2 helpers (proj kernel) ----------------
__device__ __forceinline__ void fma2(u64 &d, u64 a, u64 b) {
    asm("fma.rn.f32x2 %0, %1, %2, %0;" : "+l"(d) : "l"(a), "l"(b));
}
__device__ __forceinline__ float2 up2(u64 v) {
    float2 f; asm("mov.b64 {%0, %1}, %2;" : "=f"(f.x), "=f"(f.y) : "l"(v)); return f;
}

__device__ __forceinline__ uint32_t smem_u32(const void* p) {
    uint32_t a;
    asm("{ .reg .u64 t; cvta.to.shared.u64 t, %1; cvt.u32.u64 %0, t; }" : "=r"(a) : "l"(p));
    return a;
}
__device__ __forceinline__ void cpasync16(uint32_t dst, const void* src) {
    asm volatile("cp.async.cg.shared.global [%0], [%1], 16;" :: "r"(dst), "l"(src));
}
__device__ __forceinline__ void cpasync_commit_wait() {
    asm volatile("cp.async.commit_group;");
    asm volatile("cp.async.wait_group 0;" ::: "memory");
}

// ---------------- group barrier: 4 independent groups of 32 CTAs ----------------
__device__ __forceinline__ void gsync(unsigned gen, int gbase) {
    __syncthreads();
    if (threadIdx.x == 0) {
        __threadfence();                 // release prior global writes
        g_flags[blockIdx.x] = gen;       // volatile store
    }
    if (threadIdx.x < 32) {
        while (g_flags[gbase + threadIdx.x] < gen) { }
    }
    __syncthreads();
}

// ---------------- bf16 helpers ----------------
__device__ __forceinline__ void bsplit(float f, uint16_t &hi, uint16_t &lo) {
    __nv_bfloat16 h = __float2bfloat16_rn(f);
    float r = f - __bfloat162float(h);
    __nv_bfloat16 l = __float2bfloat16_rn(r);
    hi = *(uint16_t*)&h;
    lo = *(uint16_t*)&l;
}
__device__ __forceinline__ uint32_t pack16(uint16_t a, uint16_t b) {
    return (uint32_t)a | ((uint32_t)b << 16);
}

// mma.m16n8k16 row.col bf16 -> f32
__device__ __forceinline__ void mma16816(float* d, const uint32_t* a, const uint32_t* b) {
    asm volatile(
        "mma.sync.aligned.m16n8k16.row.col.f32.bf16.bf16.f32 "
        "{%0,%1,%2,%3}, {%4,%5,%6,%7}, {%8,%9}, {%0,%1,%2,%3};"
        : "+f"(d[0]), "+f"(d[1]), "+f"(d[2]), "+f"(d[3])
        : "r"(a[0]), "r"(a[1]), "r"(a[2]), "r"(a[3]), "r"(b[0]), "r"(b[1]));
}

// ============================================================================
// Projection GEMM: C[32768][1024] = A[32768][K] @ W[1024][K]^T + (bi + bh)
// (unchanged from R5)
// ============================================================================
__global__ void __launch_bounds__(256, 2) proj_kernel(
    const float* __restrict__ A, const float* __restrict__ W,
    const float* __restrict__ bi, const float* __restrict__ bh,
    float* __restrict__ C, int K)
{
    __shared__ __align__(16) float sA[16 * 132];
    __shared__ __align__(16) float sB[16 * 132];

    const int tid = threadIdx.x;
    const int tm = blockIdx.x >> 3;
    const int tn = blockIdx.x & 7;
    const int ty = tid >> 4;
    const int tx = tid & 15;
    const int lr = tid >> 2;
    const int lq = tid & 3;

    u64 acc[8][4];
    #pragma unroll
    for (int i = 0; i < 8; i++)
        #pragma unroll
        for (int j = 0; j < 4; j++) acc[i][j] = 0ull;

    const float* Ab = A + (size_t)(tm * 128) * K;
    const float* Wb = W + (size_t)(tn * 128) * K;

    for (int kc = 0; kc < K; kc += 16) {
        __syncthreads();
        #pragma unroll
        for (int p = 0; p < 2; p++) {
            const int rr = lr + p * 64;
            const float4 a4 = __ldg((const float4*)(Ab + (size_t)rr * K + kc + lq * 4));
            const float4 w4 = __ldg((const float4*)(Wb + (size_t)rr * K + kc + lq * 4));
            sA[(lq * 4 + 0) * 132 + rr] = a4.x;
            sA[(lq * 4 + 1) * 132 + rr] = a4.y;
            sA[(lq * 4 + 2) * 132 + rr] = a4.z;
            sA[(lq * 4 + 3) * 132 + rr] = a4.w;
            sB[(lq * 4 + 0) * 132 + rr] = w4.x;
            sB[(lq * 4 + 1) * 132 + rr] = w4.y;
            sB[(lq * 4 + 2) * 132 + rr] = w4.z;
            sB[(lq * 4 + 3) * 132 + rr] = w4.w;
        }
        __syncthreads();
        #pragma unroll
        for (int kk = 0; kk < 16; kk++) {
            const float4 a0 = *(const float4*)&sA[kk * 132 + ty * 4];
            const float4 a1 = *(const float4*)&sA[kk * 132 + 64 + ty * 4];
            const ulonglong2 bq0 = *(const ulonglong2*)&sB[kk * 132 + tx * 4];
            const ulonglong2 bq1 = *(const ulonglong2*)&sB[kk * 132 + 64 + tx * 4];
            const float am[8] = {a0.x, a0.y, a0.z, a0.w, a1.x, a1.y, a1.z, a1.w};
            #pragma unroll
            for (int i = 0; i < 8; i++) {
                u64 ad;
                asm("mov.b64 %0, {%1, %1};" : "=l"(ad) : "f"(am[i]));
                fma2(acc[i][0], ad, bq0.x);
                fma2(acc[i][1], ad, bq0.y);
                fma2(acc[i][2], ad, bq1.x);
                fma2(acc[i][3], ad, bq1.y);
            }
        }
    }

    const int n0 = tn * 128 + tx * 4;
    const int n1 = n0 + 64;
    float4 bia0, bia1;
    {
        const float4 i0 = __ldg((const float4*)(bi + n0));
        const float4 h0 = __ldg((const float4*)(bh + n0));
        const float4 i1 = __ldg((const float4*)(bi + n1));
        const float4 h1 = __ldg((const float4*)(bh + n1));
        bia0 = make_float4(i0.x + h0.x, i0.y + h0.y, i0.z + h0.z, i0.w + h0.w);
        bia1 = make_float4(i1.x + h1.x, i1.y + h1.y, i1.z + h1.z, i1.w + h1.w);
    }
    #pragma unroll
    for (int i = 0; i < 8; i++) {
        const int m = tm * 128 + (i < 4 ? ty * 4 + i : 64 + ty * 4 + (i - 4));
        const float2 c0 = up2(acc[i][0]), c1 = up2(acc[i][1]);
        const float2 c2 = up2(acc[i][2]), c3 = up2(acc[i][3]);
        *(float4*)(C + (size_t)m * HDIM + n0) =
            make_float4(c0.x + bia0.x, c0.y + bia0.y, c1.x + bia0.z, c1.y + bia0.w);
        *(float4*)(C + (size_t)m * HDIM + n1) =
            make_float4(c2.x + bia1.x, c2.y + bia1.y, c3.x + bia1.z, c3.y + bia1.w);
    }
}

// ============================================================================
// Recurrent scan on TENSOR CORES (bf16 4-term split = fp32-accurate).
// 128 CTAs x 256 thr (8 warps), 1 CTA/SM, CTA tile [16b x 32o].
// Warp w owns k-slice [128w,+128). Per warp: 4 n-subtiles (8 o each),
// 8 k-steps of mma.m16n8k16, 4 combos (hi/lo x hi/lo) into fp32 acc.
// W hi/lo fragments built ONCE per layer into registers by lane formula.
// h published as bf16 hi/lo planes (parity ring); staged 64KB/step (cp.async).
// smem A planes padded to 1032 halves/row -> conflict-free LDS.32.
// Reduce: 8 warp-partials in smem f32, final pass per thread. Group barrier.
// ============================================================================
#define SHI_OFF 0
#define SLO_OFF 33024                       // 16*1032*2
#define RED_OFF 66048                       // + 16*1032*2
#define SCAN_SMEM_BYTES (66048 + 8 * 512 * 4)   // 82,432 B

__global__ void __launch_bounds__(256, 1) scan_kernel(
    const float* __restrict__ P, float* __restrict__ S,
    const float* __restrict__ Whh)
{
    extern __shared__ __align__(16) char smx[];
    uint16_t* sHi = (uint16_t*)(smx + SHI_OFF);   // [16][1032] bf16
    uint16_t* sLo = (uint16_t*)(smx + SLO_OFF);   // [16][1032] bf16
    float*    red = (float*)(smx + RED_OFF);      // [8][512] f32

    const int tid  = threadIdx.x;
    const int cta  = blockIdx.x;
    const int gbase = cta & ~31;
    const int b0 = (cta >> 5) * 16;      // batch block
    const int o0 = (cta & 31) * 32;      // output block
    const int warp = tid >> 5;           // k-slice [warp*128,+128)
    const int lane = tid & 31;
    const int kb = warp * 128;
    const int lg = lane >> 2;            // group id (row / col in frags)
    const int lt = lane & 3;             // thread in group

    // ---- build W hi/lo B-fragments in registers (once per layer) ----
    // B col-major [k16 x n8]: lane holds {B[k][n],B[k+1][n]} k=(lane&3)*2 (+8)
    uint32_t bh[4][8][2], bl[4][8][2];
    #pragma unroll
    for (int nt = 0; nt < 4; nt++) {
        const int n = o0 + nt * 8 + lg;
        #pragma unroll
        for (int ks = 0; ks < 8; ks++) {
            const int kk = kb + ks * 16 + lt * 2;
            const float* wr = Whh + (size_t)n * HDIM + kk;
            const float w0 = __ldg(wr),     w1 = __ldg(wr + 1);
            const float w8 = __ldg(wr + 8), w9 = __ldg(wr + 9);
            uint16_t h0, l0, h1, l1, h8, l8, h9, l9;
            bsplit(w0, h0, l0); bsplit(w1, h1, l1);
            bsplit(w8, h8, l8); bsplit(w9, h9, l9);
            bh[nt][ks][0] = pack16(h0, h1); bh[nt][ks][1] = pack16(h8, h9);
            bl[nt][ks][0] = pack16(l0, l1); bl[nt][ks][1] = pack16(l8, l9);
        }
    }

    unsigned gen = g_flags[cta];

    // Epilogue mapping: 2 adjacent outputs per thread
    const int pb = tid >> 4;
    const int po = (tid & 15) * 2;
    const size_t prow = ((size_t)(b0 + pb) * SEQT) * HDIM + o0 + po;
    const size_t hidx = (size_t)(b0 + pb) * HDIM + o0 + po;   // plane index

    // t = 0: h = relu(pre); publish fp32 + bf16 planes (slot 0)
    {
        const float2 p2 = *(const float2*)(P + prow);
        const float h0 = fmaxf(p2.x, 0.f), h1 = fmaxf(p2.y, 0.f);
        *(float2*)(S + prow) = make_float2(h0, h1);
        uint16_t a, b, c, d;
        bsplit(h0, a, b); bsplit(h1, c, d);
        *(uint32_t*)&g_Hhi[0][hidx] = pack16(a, c);
        *(uint32_t*)&g_Hlo[0][hidx] = pack16(b, d);
    }
    gen++; gsync(gen, gbase);

    const uint32_t sHi_a = smem_u32(sHi);
    const uint32_t sLo_a = smem_u32(sLo);

    for (int t = 1; t < SEQT; t++) {
        const float2 p2 = __ldg((const float2*)(P + prow + (size_t)t * HDIM));
        const int sr = (t - 1) & 1;     // read slot
        const int sw = t & 1;           // write slot

        // ---- stage bf16 planes: 2 planes x 16 rows x 2KB = 4096 x 16B ----
        {
            #pragma unroll
            for (int p = 0; p < 16; p++) {
                const int i = p * 256 + tid;          // 0..4095
                const int plane = i >> 11;
                const int j  = i & 2047;
                const int bb = j >> 7;                // 0..15
                const int c  = j & 127;               // 16B chunk
                const __nv_bfloat16* src =
                    (plane ? g_Hlo[sr] : g_Hhi[sr]) + (size_t)(b0 + bb) * HDIM + c * 8;
                const uint32_t dst =
                    (plane ? sLo_a : sHi_a) + (uint32_t)(bb * 1032 + c * 8) * 2;
                cpasync16(dst, src);
            }
            cpasync_commit_wait();
        }
        __syncthreads();

        // ---- tensor-core compute: 8 k-steps x 4 n-tiles x 4 combos ----
        float d[4][4];
        #pragma unroll
        for (int nt = 0; nt < 4; nt++)
            #pragma unroll
            for (int r = 0; r < 4; r++) d[nt][r] = 0.f;

        #pragma unroll
        for (int ks = 0; ks < 8; ks++) {
            const int k0 = kb + ks * 16 + lt * 2;
            uint32_t ahi[4], alo[4];
            ahi[0] = *(const uint32_t*)(sHi + lg * 1032 + k0);
            ahi[1] = *(const uint32_t*)(sHi + (lg + 8) * 1032 + k0);
            ahi[2] = *(const uint32_t*)(sHi + lg * 1032 + k0 + 8);
            ahi[3] = *(const uint32_t*)(sHi + (lg + 8) * 1032 + k0 + 8);
            alo[0] = *(const uint32_t*)(sLo + lg * 1032 + k0);
            alo[1] = *(const uint32_t*)(sLo + (lg + 8) * 1032 + k0);
            alo[2] = *(const uint32_t*)(sLo + lg * 1032 + k0 + 8);
            alo[3] = *(const uint32_t*)(sLo + (lg + 8) * 1032 + k0 + 8);
            #pragma unroll
            for (int nt = 0; nt < 4; nt++) {
                mma16816(d[nt], ahi, bh[nt][ks]);
                mma16816(d[nt], ahi, bl[nt][ks]);
                mma16816(d[nt], alo, bh[nt][ks]);
                mma16816(d[nt], alo, bl[nt][ks]);
            }
        }

        // ---- stash warp partials: red[warp][b*32 + o_local] ----
        #pragma unroll
        for (int nt = 0; nt < 4; nt++) {
            const int oc = nt * 8 + lt * 2;
            *(float2*)&red[warp * 512 + lg * 32 + oc]       = make_float2(d[nt][0], d[nt][1]);
            *(float2*)&red[warp * 512 + (lg + 8) * 32 + oc] = make_float2(d[nt][2], d[nt][3]);
        }
        __syncthreads();

        // ---- final reduce over 8 warps, relu, publish ----
        {
            float s0 = 0.f, s1 = 0.f;
            #pragma unroll
            for (int w8 = 0; w8 < 8; w8++) {
                const float2 v = *(const float2*)&red[w8 * 512 + pb * 32 + po];
                s0 += v.x; s1 += v.y;
            }
            const float h0 = fmaxf(s0 + p2.x, 0.f);
            const float h1 = fmaxf(s1 + p2.y, 0.f);
            *(float2*)(S + prow + (size_t)t * HDIM) = make_float2(h0, h1);
            uint16_t a, b, c, dd;
            bsplit(h0, a, b); bsplit(h1, c, dd);
            *(uint32_t*)&g_Hhi[sw][hidx] = pack16(a, c);
            *(uint32_t*)&g_Hlo[sw][hidx] = pack16(b, dd);
        }
        gen++; gsync(gen, gbase);
    }
}

// ============================================================================
// FC: out[64][128] = S[:, T-1, :] @ fc_w^T + fc_b
// ============================================================================
__global__ void __launch_bounds__(128) fc_kernel(
    const float* __restrict__ S, const float* __restrict__ fw,
    const float* __restrict__ fb, float* __restrict__ out)
{
    __shared__ __align__(16) float sx[HDIM];
    const int b = blockIdx.x, tid = threadIdx.x;
    const float* xrow = S + ((size_t)b * SEQT + (SEQT - 1)) * HDIM;
    for (int i = tid; i < HDIM / 4; i += 128)
        *(float4*)&sx[i * 4] = __ldcg((const float4*)(xrow + i * 4));
    __syncthreads();
    float acc = 0.f;
    const float* wrow = fw + (size_t)tid * HDIM;
    #pragma unroll 8
    for (int q = 0; q < HDIM / 4; q++) {
        const float4 w4 = __ldg((const float4*)(wrow + q * 4));
        const float4 x4 = *(const float4*)&sx[q * 4];
        acc += w4.x * x4.x + w4.y * x4.y + w4.z * x4.z + w4.w * x4.w;
    }
    out[(size_t)b * DOUT + tid] = acc + __ldg(fb + tid);
}

// ============================================================================
extern "C" void kernel_launch(void* const* d_in, const int* in_sizes, int n_in,
                              void* d_out, int out_size)
{
    const float* x    = (const float*)d_in[0];   // [64,512,256]
    const float* wih0 = (const float*)d_in[1];   // [1024,256]
    const float* wihr = (const float*)d_in[2];   // [2,1024,1024]
    const float* whh  = (const float*)d_in[3];   // [3,1024,1024]
    const float* bih  = (const float*)d_in[4];   // [3,1024]
    const float* bhh  = (const float*)d_in[5];   // [3,1024]
    const float* fcw  = (const float*)d_in[6];   // [128,1024]
    const float* fcb  = (const float*)d_in[7];   // [128]
    float* out = (float*)d_out;                  // [64,128]

    cudaFuncSetAttribute(scan_kernel, cudaFuncAttributeMaxDynamicSharedMemorySize,
                         SCAN_SMEM_BYTES);

    void *pP = nullptr, *pS = nullptr;
    cudaGetSymbolAddress(&pP, g_P);
    cudaGetSymbolAddress(&pS, g_S);
    float* P  = (float*)pP;
    float* Sq = (float*)pS;

    proj_kernel<<<2048, 256>>>(x, wih0, bih, bhh, P, DIN);
    scan_kernel<<<GRID, 256, SCAN_SMEM_BYTES>>>(P, Sq, whh);
    proj_kernel<<<2048, 256>>>(Sq, wihr, bih + HDIM, bhh + HDIM, P, HDIM);
    scan_kernel<<<GRID, 256, SCAN_SMEM_BYTES>>>(P, Sq, whh + (size_t)HDIM * HDIM);
    proj_kernel<<<2048, 256>>>(Sq, wihr + (size_t)HDIM * HDIM, bih + 2 * HDIM, bhh + 2 * HDIM, P, HDIM);
    scan_kernel<<<GRID, 256, SCAN_SMEM_BYTES>>>(P, Sq, whh + 2 * (size_t)HDIM * HDIM);
    fc_kernel<<<BATCH, 128>>>(Sq, fcw, fcb, out);
}

// round 12
// speedup vs baseline: 2.7731x; 1.0494x over previous
#include <cuda_runtime.h>
#include <cuda_bf16.h>
#include <cstdint>
#include <cstddef>

#define BATCH 64
#define SEQT  512
#define DIN   256
#define HDIM  1024
#define DOUT  128
#define GRID  128

#define HP_STRIDE 2056        // halves per published h row (4112 B, ≡16 mod 128 banks)

typedef unsigned long long u64;

// ---------------- scratch (device globals: allocation-free) ----------------
__device__ __align__(16) static float g_P[(size_t)BATCH * SEQT * HDIM]; // pre-activations
__device__ __align__(16) static float g_S[(size_t)BATCH * SEQT * HDIM]; // layer outputs / h
__device__ __align__(16) static __nv_bfloat16 g_Hp[2][(size_t)BATCH * HP_STRIDE]; // h planes
__device__ volatile unsigned g_flags[GRID];                             // barrier flags

// ---------------- packed f32x2 helpers (proj kernel) ----------------
__device__ __forceinline__ void fma2(u64 &d, u64 a, u64 b) {
    asm("fma.rn.f32x2 %0, %1, %2, %0;" : "+l"(d) : "l"(a), "l"(b));
}
__device__ __forceinline__ float2 up2(u64 v) {
    float2 f; asm("mov.b64 {%0, %1}, %2;" : "=f"(f.x), "=f"(f.y) : "l"(v)); return f;
}

__device__ __forceinline__ uint32_t smem_u32(const void* p) {
    uint32_t a;
    asm("{ .reg .u64 t; cvta.to.shared.u64 t, %1; cvt.u32.u64 %0, t; }" : "=r"(a) : "l"(p));
    return a;
}

// ---------------- mbarrier + TMA bulk helpers ----------------
__device__ __forceinline__ void mbar_init(uint32_t a, uint32_t cnt) {
    asm volatile("mbarrier.init.shared.b64 [%0], %1;" :: "r"(a), "r"(cnt) : "memory");
}
__device__ __forceinline__ void fence_proxy_async_shared() {
    asm volatile("fence.proxy.async.shared::cta;" ::: "memory");
}
__device__ __forceinline__ void mbar_expect_tx(uint32_t a, uint32_t bytes) {
    asm volatile("mbarrier.arrive.expect_tx.shared.b64 _, [%0], %1;"
                 :: "r"(a), "r"(bytes) : "memory");
}
__device__ __forceinline__ void bulk_g2s(uint32_t dst, const void* src,
                                         uint32_t bytes, uint32_t mbar) {
    asm volatile(
        "cp.async.bulk.shared::cta.global.mbarrier::complete_tx::bytes [%0], [%1], %2, [%3];"
        :: "r"(dst), "l"(src), "r"(bytes), "r"(mbar) : "memory");
}
__device__ __forceinline__ void mbar_wait(uint32_t a, uint32_t ph) {
    asm volatile(
        "{\n\t"
        ".reg .pred P;\n\t"
        "W_%=:\n\t"
        "mbarrier.try_wait.parity.acquire.cta.shared::cta.b64 P, [%0], %1;\n\t"
        "@P bra D_%=;\n\t"
        "bra W_%=;\n\t"
        "D_%=:\n\t"
        "}"
        :: "r"(a), "r"(ph) : "memory");
}

// ---------------- group barrier: 4 independent groups of 32 CTAs ----------------
__device__ __forceinline__ void gsync(unsigned gen, int gbase) {
    __syncthreads();
    if (threadIdx.x == 0) {
        __threadfence();                 // release prior global writes
        g_flags[blockIdx.x] = gen;       // volatile store
    }
    if (threadIdx.x < 32) {
        while (g_flags[gbase + threadIdx.x] < gen) { }
    }
    __syncthreads();
}

// ---------------- bf16 helpers ----------------
__device__ __forceinline__ void bsplit(float f, uint16_t &hi, uint16_t &lo) {
    __nv_bfloat16 h = __float2bfloat16_rn(f);
    float r = f - __bfloat162float(h);
    __nv_bfloat16 l = __float2bfloat16_rn(r);
    hi = *(uint16_t*)&h;
    lo = *(uint16_t*)&l;
}
__device__ __forceinline__ uint32_t pack16(uint16_t a, uint16_t b) {
    return (uint32_t)a | ((uint32_t)b << 16);
}

// mma.m16n8k16 row.col bf16 -> f32
__device__ __forceinline__ void mma16816(float* d, const uint32_t* a, const uint32_t* b) {
    asm volatile(
        "mma.sync.aligned.m16n8k16.row.col.f32.bf16.bf16.f32 "
        "{%0,%1,%2,%3}, {%4,%5,%6,%7}, {%8,%9}, {%0,%1,%2,%3};"
        : "+f"(d[0]), "+f"(d[1]), "+f"(d[2]), "+f"(d[3])
        : "r"(a[0]), "r"(a[1]), "r"(a[2]), "r"(a[3]), "r"(b[0]), "r"(b[1]));
}

// ============================================================================
// Projection GEMM: C[32768][1024] = A[32768][K] @ W[1024][K]^T + (bi + bh)
// ============================================================================
__global__ void __launch_bounds__(256, 2) proj_kernel(
    const float* __restrict__ A, const float* __restrict__ W,
    const float* __restrict__ bi, const float* __restrict__ bh,
    float* __restrict__ C, int K)
{
    __shared__ __align__(16) float sA[16 * 132];
    __shared__ __align__(16) float sB[16 * 132];

    const int tid = threadIdx.x;
    const int tm = blockIdx.x >> 3;
    const int tn = blockIdx.x & 7;
    const int ty = tid >> 4;
    const int tx = tid & 15;
    const int lr = tid >> 2;
    const int lq = tid & 3;

    u64 acc[8][4];
    #pragma unroll
    for (int i = 0; i < 8; i++)
        #pragma unroll
        for (int j = 0; j < 4; j++) acc[i][j] = 0ull;

    const float* Ab = A + (size_t)(tm * 128) * K;
    const float* Wb = W + (size_t)(tn * 128) * K;

    for (int kc = 0; kc < K; kc += 16) {
        __syncthreads();
        #pragma unroll
        for (int p = 0; p < 2; p++) {
            const int rr = lr + p * 64;
            const float4 a4 = __ldg((const float4*)(Ab + (size_t)rr * K + kc + lq * 4));
            const float4 w4 = __ldg((const float4*)(Wb + (size_t)rr * K + kc + lq * 4));
            sA[(lq * 4 + 0) * 132 + rr] = a4.x;
            sA[(lq * 4 + 1) * 132 + rr] = a4.y;
            sA[(lq * 4 + 2) * 132 + rr] = a4.z;
            sA[(lq * 4 + 3) * 132 + rr] = a4.w;
            sB[(lq * 4 + 0) * 132 + rr] = w4.x;
            sB[(lq * 4 + 1) * 132 + rr] = w4.y;
            sB[(lq * 4 + 2) * 132 + rr] = w4.z;
            sB[(lq * 4 + 3) * 132 + rr] = w4.w;
        }
        __syncthreads();
        #pragma unroll
        for (int kk = 0; kk < 16; kk++) {
            const float4 a0 = *(const float4*)&sA[kk * 132 + ty * 4];
            const float4 a1 = *(const float4*)&sA[kk * 132 + 64 + ty * 4];
            const ulonglong2 bq0 = *(const ulonglong2*)&sB[kk * 132 + tx * 4];
            const ulonglong2 bq1 = *(const ulonglong2*)&sB[kk * 132 + 64 + tx * 4];
            const float am[8] = {a0.x, a0.y, a0.z, a0.w, a1.x, a1.y, a1.z, a1.w};
            #pragma unroll
            for (int i = 0; i < 8; i++) {
                u64 ad;
                asm("mov.b64 %0, {%1, %1};" : "=l"(ad) : "f"(am[i]));
                fma2(acc[i][0], ad, bq0.x);
                fma2(acc[i][1], ad, bq0.y);
                fma2(acc[i][2], ad, bq1.x);
                fma2(acc[i][3], ad, bq1.y);
            }
        }
    }

    const int n0 = tn * 128 + tx * 4;
    const int n1 = n0 + 64;
    float4 bia0, bia1;
    {
        const float4 i0 = __ldg((const float4*)(bi + n0));
        const float4 h0 = __ldg((const float4*)(bh + n0));
        const float4 i1 = __ldg((const float4*)(bi + n1));
        const float4 h1 = __ldg((const float4*)(bh + n1));
        bia0 = make_float4(i0.x + h0.x, i0.y + h0.y, i0.z + h0.z, i0.w + h0.w);
        bia1 = make_float4(i1.x + h1.x, i1.y + h1.y, i1.z + h1.z, i1.w + h1.w);
    }
    #pragma unroll
    for (int i = 0; i < 8; i++) {
        const int m = tm * 128 + (i < 4 ? ty * 4 + i : 64 + ty * 4 + (i - 4));
        const float2 c0 = up2(acc[i][0]), c1 = up2(acc[i][1]);
        const float2 c2 = up2(acc[i][2]), c3 = up2(acc[i][3]);
        *(float4*)(C + (size_t)m * HDIM + n0) =
            make_float4(c0.x + bia0.x, c0.y + bia0.y, c1.x + bia0.z, c1.y + bia0.w);
        *(float4*)(C + (size_t)m * HDIM + n1) =
            make_float4(c2.x + bia1.x, c2.y + bia1.y, c3.x + bia1.z, c3.y + bia1.w);
    }
}

// ============================================================================
// Recurrent scan on TENSOR CORES — TMA-bulk staging of padded bf16 planes.
// 128 CTAs x 256 thr (8 warps), 1 CTA/SM, CTA tile [16b x 32o].
// h published as g_Hp[parity][b][2056]: hi at [0,1024), lo at [1024,2048).
// Staging = 16 cp.async.bulk of 4112B -> smem rows with 4112B stride; row
// stride ≡ 16 mod 128 banks => a-frag LDS.32 (banks lg*4+lt) conflict-free.
// 3-term split MMA (hi*bh, hi*bl, lo*bh); lo*lo dropped (~2^-32, negligible).
// ============================================================================
#define SM_SH   0                              // sH[16][2056] halves (65792 B)
#define SM_RED  65792                          // red f32[8][512] (16384 B)
#define SM_MB   (65792 + 16384)                // mbarrier (8 B)
#define SCAN_SMEM_BYTES (65792 + 16384 + 16)   // 82,192 B

__global__ void __launch_bounds__(256, 1) scan_kernel(
    const float* __restrict__ P, float* __restrict__ S,
    const float* __restrict__ Whh)
{
    extern __shared__ __align__(16) char smx[];
    uint16_t* sH  = (uint16_t*)(smx + SM_SH);
    float*    red = (float*)(smx + SM_RED);
    const uint32_t mb   = smem_u32(smx + SM_MB);
    const uint32_t sH_a = smem_u32(sH);

    const int tid  = threadIdx.x;
    const int cta  = blockIdx.x;
    const int gbase = cta & ~31;
    const int b0 = (cta >> 5) * 16;      // batch block
    const int o0 = (cta & 31) * 32;      // output block
    const int warp = tid >> 5;           // k-slice [warp*128,+128)
    const int lane = tid & 31;
    const int kb = warp * 128;
    const int lg = lane >> 2;            // group id
    const int lt = lane & 3;             // thread in group

    // ---- build W hi/lo B-fragments in registers (once per layer) ----
    uint32_t bh[4][8][2], bl[4][8][2];
    #pragma unroll
    for (int nt = 0; nt < 4; nt++) {
        const int n = o0 + nt * 8 + lg;
        #pragma unroll
        for (int ks = 0; ks < 8; ks++) {
            const int kk = kb + ks * 16 + lt * 2;
            const float* wr = Whh + (size_t)n * HDIM + kk;
            const float w0 = __ldg(wr),     w1 = __ldg(wr + 1);
            const float w8 = __ldg(wr + 8), w9 = __ldg(wr + 9);
            uint16_t h0, l0, h1, l1, h8, l8, h9, l9;
            bsplit(w0, h0, l0); bsplit(w1, h1, l1);
            bsplit(w8, h8, l8); bsplit(w9, h9, l9);
            bh[nt][ks][0] = pack16(h0, h1); bh[nt][ks][1] = pack16(h8, h9);
            bl[nt][ks][0] = pack16(l0, l1); bl[nt][ks][1] = pack16(l8, l9);
        }
    }

    if (tid == 0) {
        mbar_init(mb, 1);
        fence_proxy_async_shared();
    }

    unsigned gen = g_flags[cta];

    // Epilogue mapping: 2 adjacent outputs per thread
    const int pb = tid >> 4;
    const int po = (tid & 15) * 2;
    const size_t prow = ((size_t)(b0 + pb) * SEQT) * HDIM + o0 + po;
    const size_t hrow = (size_t)(b0 + pb) * HP_STRIDE + o0 + po;

    // t = 0: h = relu(pre); publish fp32 + planes (slot 0)
    {
        const float2 p2 = *(const float2*)(P + prow);
        const float h0 = fmaxf(p2.x, 0.f), h1 = fmaxf(p2.y, 0.f);
        *(float2*)(S + prow) = make_float2(h0, h1);
        uint16_t a, b, c, d;
        bsplit(h0, a, b); bsplit(h1, c, d);
        *(uint32_t*)&g_Hp[0][hrow]        = pack16(a, c);
        *(uint32_t*)&g_Hp[0][hrow + 1024] = pack16(b, d);
    }
    gen++; gsync(gen, gbase);   // also covers mbar_init visibility

    for (int t = 1; t < SEQT; t++) {
        const float2 p2 = __ldg((const float2*)(P + prow + (size_t)t * HDIM));
        const int sr = (t - 1) & 1;     // read slot
        const int sw = t & 1;           // write slot

        // ---- TMA bulk staging: 16 rows x 4112 B ----
        if (tid == 0) {
            mbar_expect_tx(mb, 16 * 4112);
            const __nv_bfloat16* src0 = g_Hp[sr] + (size_t)b0 * HP_STRIDE;
            #pragma unroll
            for (int bb = 0; bb < 16; bb++)
                bulk_g2s(sH_a + bb * 4112,
                         src0 + (size_t)bb * HP_STRIDE, 4112, mb);
        }
        mbar_wait(mb, (t - 1) & 1);

        // ---- tensor-core compute: 8 k-steps x 4 n-tiles x 3 combos ----
        float d[4][4];
        #pragma unroll
        for (int nt = 0; nt < 4; nt++)
            #pragma unroll
            for (int r = 0; r < 4; r++) d[nt][r] = 0.f;

        #pragma unroll
        for (int ks = 0; ks < 8; ks++) {
            const int k0 = kb + ks * 16 + lt * 2;
            uint32_t ahi[4], alo[4];
            ahi[0] = *(const uint32_t*)(sH + lg * HP_STRIDE + k0);
            ahi[1] = *(const uint32_t*)(sH + (lg + 8) * HP_STRIDE + k0);
            ahi[2] = *(const uint32_t*)(sH + lg * HP_STRIDE + k0 + 8);
            ahi[3] = *(const uint32_t*)(sH + (lg + 8) * HP_STRIDE + k0 + 8);
            alo[0] = *(const uint32_t*)(sH + lg * HP_STRIDE + 1024 + k0);
            alo[1] = *(const uint32_t*)(sH + (lg + 8) * HP_STRIDE + 1024 + k0);
            alo[2] = *(const uint32_t*)(sH + lg * HP_STRIDE + 1024 + k0 + 8);
            alo[3] = *(const uint32_t*)(sH + (lg + 8) * HP_STRIDE + 1024 + k0 + 8);
            #pragma unroll
            for (int nt = 0; nt < 4; nt++) {
                mma16816(d[nt], ahi, bh[nt][ks]);
                mma16816(d[nt], ahi, bl[nt][ks]);
                mma16816(d[nt], alo, bh[nt][ks]);
            }
        }

        // ---- stash warp partials ----
        #pragma unroll
        for (int nt = 0; nt < 4; nt++) {
            const int oc = nt * 8 + lt * 2;
            *(float2*)&red[warp * 512 + lg * 32 + oc]       = make_float2(d[nt][0], d[nt][1]);
            *(float2*)&red[warp * 512 + (lg + 8) * 32 + oc] = make_float2(d[nt][2], d[nt][3]);
        }
        __syncthreads();

        // ---- final reduce over 8 warps, relu, publish ----
        {
            float s0 = 0.f, s1 = 0.f;
            #pragma unroll
            for (int w8 = 0; w8 < 8; w8++) {
                const float2 v = *(const float2*)&red[w8 * 512 + pb * 32 + po];
                s0 += v.x; s1 += v.y;
            }
            const float h0 = fmaxf(s0 + p2.x, 0.f);
            const float h1 = fmaxf(s1 + p2.y, 0.f);
            *(float2*)(S + prow + (size_t)t * HDIM) = make_float2(h0, h1);
            uint16_t a, b, c, dd;
            bsplit(h0, a, b); bsplit(h1, c, dd);
            *(uint32_t*)&g_Hp[sw][hrow]        = pack16(a, c);
            *(uint32_t*)&g_Hp[sw][hrow + 1024] = pack16(b, dd);
        }
        gen++; gsync(gen, gbase);
    }
}

// ============================================================================
// FC: out[64][128] = S[:, T-1, :] @ fc_w^T + fc_b
// ============================================================================
__global__ void __launch_bounds__(128) fc_kernel(
    const float* __restrict__ S, const float* __restrict__ fw,
    const float* __restrict__ fb, float* __restrict__ out)
{
    __shared__ __align__(16) float sx[HDIM];
    const int b = blockIdx.x, tid = threadIdx.x;
    const float* xrow = S + ((size_t)b * SEQT + (SEQT - 1)) * HDIM;
    for (int i = tid; i < HDIM / 4; i += 128)
        *(float4*)&sx[i * 4] = __ldcg((const float4*)(xrow + i * 4));
    __syncthreads();
    float acc = 0.f;
    const float* wrow = fw + (size_t)tid * HDIM;
    #pragma unroll 8
    for (int q = 0; q < HDIM / 4; q++) {
        const float4 w4 = __ldg((const float4*)(wrow + q * 4));
        const float4 x4 = *(const float4*)&sx[q * 4];
        acc += w4.x * x4.x + w4.y * x4.y + w4.z * x4.z + w4.w * x4.w;
    }
    out[(size_t)b * DOUT + tid] = acc + __ldg(fb + tid);
}

// ============================================================================
extern "C" void kernel_launch(void* const* d_in, const int* in_sizes, int n_in,
                              void* d_out, int out_size)
{
    const float* x    = (const float*)d_in[0];   // [64,512,256]
    const float* wih0 = (const float*)d_in[1];   // [1024,256]
    const float* wihr = (const float*)d_in[2];   // [2,1024,1024]
    const float* whh  = (const float*)d_in[3];   // [3,1024,1024]
    const float* bih  = (const float*)d_in[4];   // [3,1024]
    const float* bhh  = (const float*)d_in[5];   // [3,1024]
    const float* fcw  = (const float*)d_in[6];   // [128,1024]
    const float* fcb  = (const float*)d_in[7];   // [128]
    float* out = (float*)d_out;                  // [64,128]

    cudaFuncSetAttribute(scan_kernel, cudaFuncAttributeMaxDynamicSharedMemorySize,
                         SCAN_SMEM_BYTES);

    void *pP = nullptr, *pS = nullptr;
    cudaGetSymbolAddress(&pP, g_P);
    cudaGetSymbolAddress(&pS, g_S);
    float* P  = (float*)pP;
    float* Sq = (float*)pS;

    proj_kernel<<<2048, 256>>>(x, wih0, bih, bhh, P, DIN);
    scan_kernel<<<GRID, 256, SCAN_SMEM_BYTES>>>(P, Sq, whh);
    proj_kernel<<<2048, 256>>>(Sq, wihr, bih + HDIM, bhh + HDIM, P, HDIM);
    scan_kernel<<<GRID, 256, SCAN_SMEM_BYTES>>>(P, Sq, whh + (size_t)HDIM * HDIM);
    proj_kernel<<<2048, 256>>>(Sq, wihr + (size_t)HDIM * HDIM, bih + 2 * HDIM, bhh + 2 * HDIM, P, HDIM);
    scan_kernel<<<GRID, 256, SCAN_SMEM_BYTES>>>(P, Sq, whh + 2 * (size_t)HDIM * HDIM);
    fc_kernel<<<BATCH, 128>>>(Sq, fcw, fcb, out);
}

// round 13
// speedup vs baseline: 2.9208x; 1.0533x over previous
#include <cuda_runtime.h>
#include <cuda_bf16.h>
#include <cstdint>
#include <cstddef>

#define BATCH 64
#define SEQT  512
#define DIN   256
#define HDIM  1024
#define DOUT  128
#define GRID  128

#define HP_STRIDE 2056        // halves per published h row (4112 B)

typedef unsigned long long u64;

// ---------------- scratch (device globals: allocation-free) ----------------
__device__ __align__(16) static float g_P[(size_t)BATCH * SEQT * HDIM]; // pre-activations
__device__ __align__(16) static float g_S[(size_t)BATCH * SEQT * HDIM]; // layer outputs / h
__device__ __align__(16) static __nv_bfloat16 g_Hp[2][(size_t)BATCH * HP_STRIDE]; // h planes
__device__ volatile unsigned g_flags[GRID];                             // barrier flags

__device__ __forceinline__ uint32_t smem_u32(const void* p) {
    uint32_t a;
    asm("{ .reg .u64 t; cvta.to.shared.u64 t, %1; cvt.u32.u64 %0, t; }" : "=r"(a) : "l"(p));
    return a;
}

// ---------------- mbarrier + TMA bulk helpers ----------------
__device__ __forceinline__ void mbar_init(uint32_t a, uint32_t cnt) {
    asm volatile("mbarrier.init.shared.b64 [%0], %1;" :: "r"(a), "r"(cnt) : "memory");
}
__device__ __forceinline__ void fence_proxy_async_shared() {
    asm volatile("fence.proxy.async.shared::cta;" ::: "memory");
}
__device__ __forceinline__ void mbar_expect_tx(uint32_t a, uint32_t bytes) {
    asm volatile("mbarrier.arrive.expect_tx.shared.b64 _, [%0], %1;"
                 :: "r"(a), "r"(bytes) : "memory");
}
__device__ __forceinline__ void bulk_g2s(uint32_t dst, const void* src,
                                         uint32_t bytes, uint32_t mbar) {
    asm volatile(
        "cp.async.bulk.shared::cta.global.mbarrier::complete_tx::bytes [%0], [%1], %2, [%3];"
        :: "r"(dst), "l"(src), "r"(bytes), "r"(mbar) : "memory");
}
__device__ __forceinline__ void mbar_wait(uint32_t a, uint32_t ph) {
    asm volatile(
        "{\n\t"
        ".reg .pred P;\n\t"
        "W_%=:\n\t"
        "mbarrier.try_wait.parity.acquire.cta.shared::cta.b64 P, [%0], %1;\n\t"
        "@P bra D_%=;\n\t"
        "bra W_%=;\n\t"
        "D_%=:\n\t"
        "}"
        :: "r"(a), "r"(ph) : "memory");
}

// ---------------- group barrier: 4 independent groups of 32 CTAs ----------------
__device__ __forceinline__ void gsync(unsigned gen, int gbase) {
    __syncthreads();
    if (threadIdx.x == 0) {
        __threadfence();
        g_flags[blockIdx.x] = gen;
    }
    if (threadIdx.x < 32) {
        while (g_flags[gbase + threadIdx.x] < gen) { }
    }
    __syncthreads();
}

// ---------------- bf16 helpers ----------------
__device__ __forceinline__ void bsplit(float f, uint16_t &hi, uint16_t &lo) {
    __nv_bfloat16 h = __float2bfloat16_rn(f);
    float r = f - __bfloat162float(h);
    __nv_bfloat16 l = __float2bfloat16_rn(r);
    hi = *(uint16_t*)&h;
    lo = *(uint16_t*)&l;
}
__device__ __forceinline__ uint32_t pack16(uint16_t a, uint16_t b) {
    return (uint32_t)a | ((uint32_t)b << 16);
}
__device__ __forceinline__ void split2(float x, float y, uint32_t &hp, uint32_t &lp) {
    uint16_t xh, xl, yh, yl;
    bsplit(x, xh, xl); bsplit(y, yh, yl);
    hp = pack16(xh, yh); lp = pack16(xl, yl);
}

// mma.m16n8k16 row.col bf16 -> f32
__device__ __forceinline__ void mma16816(float* d, const uint32_t* a, const uint32_t* b) {
    asm volatile(
        "mma.sync.aligned.m16n8k16.row.col.f32.bf16.bf16.f32 "
        "{%0,%1,%2,%3}, {%4,%5,%6,%7}, {%8,%9}, {%0,%1,%2,%3};"
        : "+f"(d[0]), "+f"(d[1]), "+f"(d[2]), "+f"(d[3])
        : "r"(a[0]), "r"(a[1]), "r"(a[2]), "r"(a[3]), "r"(b[0]), "r"(b[1]));
}

// ============================================================================
// TENSOR projection GEMM (bf16 3-term split, fp32-grade):
// C[32768][1024] = A[32768][K] @ W[1024][K]^T + (bi + bh)
// CTA tile 128x128, 8 warps (2m x 4n), warp tile 64x32, K-chunk 16.
// fp32 streamed, split in-loop, smem pitch 40 halves (conflict-free frags).
// Next chunk's LDG prefetched into registers before current chunk's MMAs.
// ============================================================================
#define PJP 40    // smem pitch in halves

__global__ void __launch_bounds__(256, 1) proj2_kernel(
    const float* __restrict__ A, const float* __restrict__ W,
    const float* __restrict__ bi, const float* __restrict__ bh,
    float* __restrict__ C, int K)
{
    __shared__ __align__(16) uint16_t sAh[128 * PJP];
    __shared__ __align__(16) uint16_t sAl[128 * PJP];
    __shared__ __align__(16) uint16_t sWh[128 * PJP];
    __shared__ __align__(16) uint16_t sWl[128 * PJP];

    const int tid  = threadIdx.x;
    const int warp = tid >> 5;
    const int lane = tid & 31;
    const int wm = warp >> 2;        // 0..1
    const int wn = warp & 3;         // 0..3
    const int lg = lane >> 2;        // 0..7
    const int lt = lane & 3;         // 0..3
    const int tm = blockIdx.x >> 3;  // 0..255
    const int tn = blockIdx.x & 7;   // 0..7

    const int row = tid >> 1;        // 0..127  (load row)
    const int kq  = (tid & 1) * 8;   // 0 / 8   (load k-offset)

    const float* Ab = A + (size_t)(tm * 128) * K + (size_t)row * K;
    const float* Wb = W + (size_t)(tn * 128) * K + (size_t)row * K;

    float d[4][4][4];
    #pragma unroll
    for (int mi = 0; mi < 4; mi++)
        #pragma unroll
        for (int ni = 0; ni < 4; ni++)
            #pragma unroll
            for (int r = 0; r < 4; r++) d[mi][ni][r] = 0.f;

    // prefetch chunk 0
    float4 pa0 = __ldg((const float4*)(Ab + kq));
    float4 pa1 = __ldg((const float4*)(Ab + kq + 4));
    float4 pw0 = __ldg((const float4*)(Wb + kq));
    float4 pw1 = __ldg((const float4*)(Wb + kq + 4));

    for (int kc = 0; kc < K; kc += 16) {
        // split current chunk regs -> smem
        {
            uint4 hv, lv;
            split2(pa0.x, pa0.y, hv.x, lv.x); split2(pa0.z, pa0.w, hv.y, lv.y);
            split2(pa1.x, pa1.y, hv.z, lv.z); split2(pa1.z, pa1.w, hv.w, lv.w);
            *(uint4*)&sAh[row * PJP + kq] = hv;
            *(uint4*)&sAl[row * PJP + kq] = lv;
            split2(pw0.x, pw0.y, hv.x, lv.x); split2(pw0.z, pw0.w, hv.y, lv.y);
            split2(pw1.x, pw1.y, hv.z, lv.z); split2(pw1.z, pw1.w, hv.w, lv.w);
            *(uint4*)&sWh[row * PJP + kq] = hv;
            *(uint4*)&sWl[row * PJP + kq] = lv;
        }
        __syncthreads();

        // prefetch next chunk (hidden under MMAs)
        if (kc + 16 < K) {
            pa0 = __ldg((const float4*)(Ab + kc + 16 + kq));
            pa1 = __ldg((const float4*)(Ab + kc + 16 + kq + 4));
            pw0 = __ldg((const float4*)(Wb + kc + 16 + kq));
            pw1 = __ldg((const float4*)(Wb + kc + 16 + kq + 4));
        }

        // fragments
        uint32_t afh[4][4], afl[4][4];
        #pragma unroll
        for (int mi = 0; mi < 4; mi++) {
            const int m = wm * 64 + mi * 16;
            afh[mi][0] = *(const uint32_t*)&sAh[(m + lg) * PJP + lt * 2];
            afh[mi][1] = *(const uint32_t*)&sAh[(m + lg + 8) * PJP + lt * 2];
            afh[mi][2] = *(const uint32_t*)&sAh[(m + lg) * PJP + lt * 2 + 8];
            afh[mi][3] = *(const uint32_t*)&sAh[(m + lg + 8) * PJP + lt * 2 + 8];
            afl[mi][0] = *(const uint32_t*)&sAl[(m + lg) * PJP + lt * 2];
            afl[mi][1] = *(const uint32_t*)&sAl[(m + lg + 8) * PJP + lt * 2];
            afl[mi][2] = *(const uint32_t*)&sAl[(m + lg) * PJP + lt * 2 + 8];
            afl[mi][3] = *(const uint32_t*)&sAl[(m + lg + 8) * PJP + lt * 2 + 8];
        }
        uint32_t bfh[4][2], bfl[4][2];
        #pragma unroll
        for (int ni = 0; ni < 4; ni++) {
            const int n = wn * 32 + ni * 8;
            bfh[ni][0] = *(const uint32_t*)&sWh[(n + lg) * PJP + lt * 2];
            bfh[ni][1] = *(const uint32_t*)&sWh[(n + lg) * PJP + lt * 2 + 8];
            bfl[ni][0] = *(const uint32_t*)&sWl[(n + lg) * PJP + lt * 2];
            bfl[ni][1] = *(const uint32_t*)&sWl[(n + lg) * PJP + lt * 2 + 8];
        }

        #pragma unroll
        for (int mi = 0; mi < 4; mi++)
            #pragma unroll
            for (int ni = 0; ni < 4; ni++) {
                mma16816(d[mi][ni], afh[mi], bfh[ni]);
                mma16816(d[mi][ni], afh[mi], bfl[ni]);
                mma16816(d[mi][ni], afl[mi], bfh[ni]);
            }
        __syncthreads();
    }

    // epilogue: + (bi + bh), store float2 per fragment row
    #pragma unroll
    for (int ni = 0; ni < 4; ni++) {
        const int n = tn * 128 + wn * 32 + ni * 8 + lt * 2;
        const float2 bv = make_float2(__ldg(bi + n) + __ldg(bh + n),
                                      __ldg(bi + n + 1) + __ldg(bh + n + 1));
        #pragma unroll
        for (int mi = 0; mi < 4; mi++) {
            const int m = tm * 128 + wm * 64 + mi * 16 + lg;
            *(float2*)(C + (size_t)m * HDIM + n) =
                make_float2(d[mi][ni][0] + bv.x, d[mi][ni][1] + bv.y);
            *(float2*)(C + (size_t)(m + 8) * HDIM + n) =
                make_float2(d[mi][ni][2] + bv.x, d[mi][ni][3] + bv.y);
        }
    }
}

// ============================================================================
// Recurrent scan on TENSOR CORES — TMA-bulk staging (unchanged from R11)
// ============================================================================
#define SM_SH   0
#define SM_RED  65792
#define SM_MB   (65792 + 16384)
#define SCAN_SMEM_BYTES (65792 + 16384 + 16)

__global__ void __launch_bounds__(256, 1) scan_kernel(
    const float* __restrict__ P, float* __restrict__ S,
    const float* __restrict__ Whh)
{
    extern __shared__ __align__(16) char smx[];
    uint16_t* sH  = (uint16_t*)(smx + SM_SH);
    float*    red = (float*)(smx + SM_RED);
    const uint32_t mb   = smem_u32(smx + SM_MB);
    const uint32_t sH_a = smem_u32(sH);

    const int tid  = threadIdx.x;
    const int cta  = blockIdx.x;
    const int gbase = cta & ~31;
    const int b0 = (cta >> 5) * 16;
    const int o0 = (cta & 31) * 32;
    const int warp = tid >> 5;
    const int lane = tid & 31;
    const int kb = warp * 128;
    const int lg = lane >> 2;
    const int lt = lane & 3;

    uint32_t bh[4][8][2], bl[4][8][2];
    #pragma unroll
    for (int nt = 0; nt < 4; nt++) {
        const int n = o0 + nt * 8 + lg;
        #pragma unroll
        for (int ks = 0; ks < 8; ks++) {
            const int kk = kb + ks * 16 + lt * 2;
            const float* wr = Whh + (size_t)n * HDIM + kk;
            const float w0 = __ldg(wr),     w1 = __ldg(wr + 1);
            const float w8 = __ldg(wr + 8), w9 = __ldg(wr + 9);
            uint16_t h0, l0, h1, l1, h8, l8, h9, l9;
            bsplit(w0, h0, l0); bsplit(w1, h1, l1);
            bsplit(w8, h8, l8); bsplit(w9, h9, l9);
            bh[nt][ks][0] = pack16(h0, h1); bh[nt][ks][1] = pack16(h8, h9);
            bl[nt][ks][0] = pack16(l0, l1); bl[nt][ks][1] = pack16(l8, l9);
        }
    }

    if (tid == 0) {
        mbar_init(mb, 1);
        fence_proxy_async_shared();
    }

    unsigned gen = g_flags[cta];

    const int pb = tid >> 4;
    const int po = (tid & 15) * 2;
    const size_t prow = ((size_t)(b0 + pb) * SEQT) * HDIM + o0 + po;
    const size_t hrow = (size_t)(b0 + pb) * HP_STRIDE + o0 + po;

    {
        const float2 p2 = *(const float2*)(P + prow);
        const float h0 = fmaxf(p2.x, 0.f), h1 = fmaxf(p2.y, 0.f);
        *(float2*)(S + prow) = make_float2(h0, h1);
        uint16_t a, b, c, d;
        bsplit(h0, a, b); bsplit(h1, c, d);
        *(uint32_t*)&g_Hp[0][hrow]        = pack16(a, c);
        *(uint32_t*)&g_Hp[0][hrow + 1024] = pack16(b, d);
    }
    gen++; gsync(gen, gbase);

    for (int t = 1; t < SEQT; t++) {
        const float2 p2 = __ldg((const float2*)(P + prow + (size_t)t * HDIM));
        const int sr = (t - 1) & 1;
        const int sw = t & 1;

        if (tid == 0) {
            mbar_expect_tx(mb, 16 * 4112);
            const __nv_bfloat16* src0 = g_Hp[sr] + (size_t)b0 * HP_STRIDE;
            #pragma unroll
            for (int bb = 0; bb < 16; bb++)
                bulk_g2s(sH_a + bb * 4112,
                         src0 + (size_t)bb * HP_STRIDE, 4112, mb);
        }
        mbar_wait(mb, (t - 1) & 1);

        float d[4][4];
        #pragma unroll
        for (int nt = 0; nt < 4; nt++)
            #pragma unroll
            for (int r = 0; r < 4; r++) d[nt][r] = 0.f;

        #pragma unroll
        for (int ks = 0; ks < 8; ks++) {
            const int k0 = kb + ks * 16 + lt * 2;
            uint32_t ahi[4], alo[4];
            ahi[0] = *(const uint32_t*)(sH + lg * HP_STRIDE + k0);
            ahi[1] = *(const uint32_t*)(sH + (lg + 8) * HP_STRIDE + k0);
            ahi[2] = *(const uint32_t*)(sH + lg * HP_STRIDE + k0 + 8);
            ahi[3] = *(const uint32_t*)(sH + (lg + 8) * HP_STRIDE + k0 + 8);
            alo[0] = *(const uint32_t*)(sH + lg * HP_STRIDE + 1024 + k0);
            alo[1] = *(const uint32_t*)(sH + (lg + 8) * HP_STRIDE + 1024 + k0);
            alo[2] = *(const uint32_t*)(sH + lg * HP_STRIDE + 1024 + k0 + 8);
            alo[3] = *(const uint32_t*)(sH + (lg + 8) * HP_STRIDE + 1024 + k0 + 8);
            #pragma unroll
            for (int nt = 0; nt < 4; nt++) {
                mma16816(d[nt], ahi, bh[nt][ks]);
                mma16816(d[nt], ahi, bl[nt][ks]);
                mma16816(d[nt], alo, bh[nt][ks]);
            }
        }

        #pragma unroll
        for (int nt = 0; nt < 4; nt++) {
            const int oc = nt * 8 + lt * 2;
            *(float2*)&red[warp * 512 + lg * 32 + oc]       = make_float2(d[nt][0], d[nt][1]);
            *(float2*)&red[warp * 512 + (lg + 8) * 32 + oc] = make_float2(d[nt][2], d[nt][3]);
        }
        __syncthreads();

        {
            float s0 = 0.f, s1 = 0.f;
            #pragma unroll
            for (int w8 = 0; w8 < 8; w8++) {
                const float2 v = *(const float2*)&red[w8 * 512 + pb * 32 + po];
                s0 += v.x; s1 += v.y;
            }
            const float h0 = fmaxf(s0 + p2.x, 0.f);
            const float h1 = fmaxf(s1 + p2.y, 0.f);
            *(float2*)(S + prow + (size_t)t * HDIM) = make_float2(h0, h1);
            uint16_t a, b, c, dd;
            bsplit(h0, a, b); bsplit(h1, c, dd);
            *(uint32_t*)&g_Hp[sw][hrow]        = pack16(a, c);
            *(uint32_t*)&g_Hp[sw][hrow + 1024] = pack16(b, dd);
        }
        gen++; gsync(gen, gbase);
    }
}

// ============================================================================
// FC: out[64][128] = S[:, T-1, :] @ fc_w^T + fc_b
// ============================================================================
__global__ void __launch_bounds__(128) fc_kernel(
    const float* __restrict__ S, const float* __restrict__ fw,
    const float* __restrict__ fb, float* __restrict__ out)
{
    __shared__ __align__(16) float sx[HDIM];
    const int b = blockIdx.x, tid = threadIdx.x;
    const float* xrow = S + ((size_t)b * SEQT + (SEQT - 1)) * HDIM;
    for (int i = tid; i < HDIM / 4; i += 128)
        *(float4*)&sx[i * 4] = __ldcg((const float4*)(xrow + i * 4));
    __syncthreads();
    float acc = 0.f;
    const float* wrow = fw + (size_t)tid * HDIM;
    #pragma unroll 8
    for (int q = 0; q < HDIM / 4; q++) {
        const float4 w4 = __ldg((const float4*)(wrow + q * 4));
        const float4 x4 = *(const float4*)&sx[q * 4];
        acc += w4.x * x4.x + w4.y * x4.y + w4.z * x4.z + w4.w * x4.w;
    }
    out[(size_t)b * DOUT + tid] = acc + __ldg(fb + tid);
}

// ============================================================================
extern "C" void kernel_launch(void* const* d_in, const int* in_sizes, int n_in,
                              void* d_out, int out_size)
{
    const float* x    = (const float*)d_in[0];   // [64,512,256]
    const float* wih0 = (const float*)d_in[1];   // [1024,256]
    const float* wihr = (const float*)d_in[2];   // [2,1024,1024]
    const float* whh  = (const float*)d_in[3];   // [3,1024,1024]
    const float* bih  = (const float*)d_in[4];   // [3,1024]
    const float* bhh  = (const float*)d_in[5];   // [3,1024]
    const float* fcw  = (const float*)d_in[6];   // [128,1024]
    const float* fcb  = (const float*)d_in[7];   // [128]
    float* out = (float*)d_out;                  // [64,128]

    cudaFuncSetAttribute(scan_kernel, cudaFuncAttributeMaxDynamicSharedMemorySize,
                         SCAN_SMEM_BYTES);

    void *pP = nullptr, *pS = nullptr;
    cudaGetSymbolAddress(&pP, g_P);
    cudaGetSymbolAddress(&pS, g_S);
    float* P  = (float*)pP;
    float* Sq = (float*)pS;

    proj2_kernel<<<2048, 256>>>(x, wih0, bih, bhh, P, DIN);
    scan_kernel<<<GRID, 256, SCAN_SMEM_BYTES>>>(P, Sq, whh);
    proj2_kernel<<<2048, 256>>>(Sq, wihr, bih + HDIM, bhh + HDIM, P, HDIM);
    scan_kernel<<<GRID, 256, SCAN_SMEM_BYTES>>>(P, Sq, whh + (size_t)HDIM * HDIM);
    proj2_kernel<<<2048, 256>>>(Sq, wihr + (size_t)HDIM * HDIM, bih + 2 * HDIM, bhh + 2 * HDIM, P, HDIM);
    scan_kernel<<<GRID, 256, SCAN_SMEM_BYTES>>>(P, Sq, whh + 2 * (size_t)HDIM * HDIM);
    fc_kernel<<<BATCH, 128>>>(Sq, fcw, fcb, out);
}

// round 14
// speedup vs baseline: 4.2976x; 1.4714x over previous
#include <cuda_runtime.h>
#include <cuda_bf16.h>
#include <cstdint>
#include <cstddef>

#define BATCH 64
#define SEQT  512
#define DIN   256
#define HDIM  1024
#define DOUT  128
#define GRID  128

#define BLK_H 1152            // halves per published block (2304 B)

typedef unsigned long long u64;

// ---------------- scratch (device globals: allocation-free) ----------------
__device__ __align__(16) static float g_P[(size_t)BATCH * SEQT * HDIM]; // pre-activations
__device__ __align__(16) static float g_S[(size_t)BATCH * SEQT * HDIM]; // layer outputs / h
__device__ __align__(16) static __nv_bfloat16 g_Hp2[2][(size_t)GRID * BLK_H]; // h blocks
__device__ volatile unsigned g_flags[GRID];   // per-CTA progress; one 128B line per group

__device__ __forceinline__ uint32_t smem_u32(const void* p) {
    uint32_t a;
    asm("{ .reg .u64 t; cvta.to.shared.u64 t, %1; cvt.u32.u64 %0, t; }" : "=r"(a) : "l"(p));
    return a;
}

// ---------------- mbarrier + TMA bulk helpers ----------------
__device__ __forceinline__ void mbar_init(uint32_t a, uint32_t cnt) {
    asm volatile("mbarrier.init.shared.b64 [%0], %1;" :: "r"(a), "r"(cnt) : "memory");
}
__device__ __forceinline__ void fence_proxy_async_shared() {
    asm volatile("fence.proxy.async.shared::cta;" ::: "memory");
}
__device__ __forceinline__ void mbar_expect_tx(uint32_t a, uint32_t bytes) {
    asm volatile("mbarrier.arrive.expect_tx.shared.b64 _, [%0], %1;"
                 :: "r"(a), "r"(bytes) : "memory");
}
__device__ __forceinline__ void bulk_g2s(uint32_t dst, const void* src,
                                         uint32_t bytes, uint32_t mbar) {
    asm volatile(
        "cp.async.bulk.shared::cta.global.mbarrier::complete_tx::bytes [%0], [%1], %2, [%3];"
        :: "r"(dst), "l"(src), "r"(bytes), "r"(mbar) : "memory");
}
__device__ __forceinline__ void mbar_wait(uint32_t a, uint32_t ph) {
    asm volatile(
        "{\n\t"
        ".reg .pred P;\n\t"
        "W_%=:\n\t"
        "mbarrier.try_wait.parity.acquire.cta.shared::cta.b64 P, [%0], %1;\n\t"
        "@P bra D_%=;\n\t"
        "bra W_%=;\n\t"
        "D_%=:\n\t"
        "}"
        :: "r"(a), "r"(ph) : "memory");
}

// ---------------- bf16 helpers ----------------
__device__ __forceinline__ void bsplit(float f, uint16_t &hi, uint16_t &lo) {
    __nv_bfloat16 h = __float2bfloat16_rn(f);
    float r = f - __bfloat162float(h);
    __nv_bfloat16 l = __float2bfloat16_rn(r);
    hi = *(uint16_t*)&h;
    lo = *(uint16_t*)&l;
}
__device__ __forceinline__ uint32_t pack16(uint16_t a, uint16_t b) {
    return (uint32_t)a | ((uint32_t)b << 16);
}
__device__ __forceinline__ void split2(float x, float y, uint32_t &hp, uint32_t &lp) {
    uint16_t xh, xl, yh, yl;
    bsplit(x, xh, xl); bsplit(y, yh, yl);
    hp = pack16(xh, yh); lp = pack16(xl, yl);
}

// mma.m16n8k16 row.col bf16 -> f32
__device__ __forceinline__ void mma16816(float* d, const uint32_t* a, const uint32_t* b) {
    asm volatile(
        "mma.sync.aligned.m16n8k16.row.col.f32.bf16.bf16.f32 "
        "{%0,%1,%2,%3}, {%4,%5,%6,%7}, {%8,%9}, {%0,%1,%2,%3};"
        : "+f"(d[0]), "+f"(d[1]), "+f"(d[2]), "+f"(d[3])
        : "r"(a[0]), "r"(a[1]), "r"(a[2]), "r"(a[3]), "r"(b[0]), "r"(b[1]));
}

// ============================================================================
// TENSOR projection GEMM (unchanged from R12)
// ============================================================================
#define PJP 40    // smem pitch in halves

__global__ void __launch_bounds__(256, 1) proj2_kernel(
    const float* __restrict__ A, const float* __restrict__ W,
    const float* __restrict__ bi, const float* __restrict__ bh,
    float* __restrict__ C, int K)
{
    __shared__ __align__(16) uint16_t sAh[128 * PJP];
    __shared__ __align__(16) uint16_t sAl[128 * PJP];
    __shared__ __align__(16) uint16_t sWh[128 * PJP];
    __shared__ __align__(16) uint16_t sWl[128 * PJP];

    const int tid  = threadIdx.x;
    const int warp = tid >> 5;
    const int lane = tid & 31;
    const int wm = warp >> 2;
    const int wn = warp & 3;
    const int lg = lane >> 2;
    const int lt = lane & 3;
    const int tm = blockIdx.x >> 3;
    const int tn = blockIdx.x & 7;

    const int row = tid >> 1;
    const int kq  = (tid & 1) * 8;

    const float* Ab = A + (size_t)(tm * 128) * K + (size_t)row * K;
    const float* Wb = W + (size_t)(tn * 128) * K + (size_t)row * K;

    float d[4][4][4];
    #pragma unroll
    for (int mi = 0; mi < 4; mi++)
        #pragma unroll
        for (int ni = 0; ni < 4; ni++)
            #pragma unroll
            for (int r = 0; r < 4; r++) d[mi][ni][r] = 0.f;

    float4 pa0 = __ldg((const float4*)(Ab + kq));
    float4 pa1 = __ldg((const float4*)(Ab + kq + 4));
    float4 pw0 = __ldg((const float4*)(Wb + kq));
    float4 pw1 = __ldg((const float4*)(Wb + kq + 4));

    for (int kc = 0; kc < K; kc += 16) {
        {
            uint4 hv, lv;
            split2(pa0.x, pa0.y, hv.x, lv.x); split2(pa0.z, pa0.w, hv.y, lv.y);
            split2(pa1.x, pa1.y, hv.z, lv.z); split2(pa1.z, pa1.w, hv.w, lv.w);
            *(uint4*)&sAh[row * PJP + kq] = hv;
            *(uint4*)&sAl[row * PJP + kq] = lv;
            split2(pw0.x, pw0.y, hv.x, lv.x); split2(pw0.z, pw0.w, hv.y, lv.y);
            split2(pw1.x, pw1.y, hv.z, lv.z); split2(pw1.z, pw1.w, hv.w, lv.w);
            *(uint4*)&sWh[row * PJP + kq] = hv;
            *(uint4*)&sWl[row * PJP + kq] = lv;
        }
        __syncthreads();

        if (kc + 16 < K) {
            pa0 = __ldg((const float4*)(Ab + kc + 16 + kq));
            pa1 = __ldg((const float4*)(Ab + kc + 16 + kq + 4));
            pw0 = __ldg((const float4*)(Wb + kc + 16 + kq));
            pw1 = __ldg((const float4*)(Wb + kc + 16 + kq + 4));
        }

        uint32_t afh[4][4], afl[4][4];
        #pragma unroll
        for (int mi = 0; mi < 4; mi++) {
            const int m = wm * 64 + mi * 16;
            afh[mi][0] = *(const uint32_t*)&sAh[(m + lg) * PJP + lt * 2];
            afh[mi][1] = *(const uint32_t*)&sAh[(m + lg + 8) * PJP + lt * 2];
            afh[mi][2] = *(const uint32_t*)&sAh[(m + lg) * PJP + lt * 2 + 8];
            afh[mi][3] = *(const uint32_t*)&sAh[(m + lg + 8) * PJP + lt * 2 + 8];
            afl[mi][0] = *(const uint32_t*)&sAl[(m + lg) * PJP + lt * 2];
            afl[mi][1] = *(const uint32_t*)&sAl[(m + lg + 8) * PJP + lt * 2];
            afl[mi][2] = *(const uint32_t*)&sAl[(m + lg) * PJP + lt * 2 + 8];
            afl[mi][3] = *(const uint32_t*)&sAl[(m + lg + 8) * PJP + lt * 2 + 8];
        }
        uint32_t bfh[4][2], bfl[4][2];
        #pragma unroll
        for (int ni = 0; ni < 4; ni++) {
            const int n = wn * 32 + ni * 8;
            bfh[ni][0] = *(const uint32_t*)&sWh[(n + lg) * PJP + lt * 2];
            bfh[ni][1] = *(const uint32_t*)&sWh[(n + lg) * PJP + lt * 2 + 8];
            bfl[ni][0] = *(const uint32_t*)&sWl[(n + lg) * PJP + lt * 2];
            bfl[ni][1] = *(const uint32_t*)&sWl[(n + lg) * PJP + lt * 2 + 8];
        }

        #pragma unroll
        for (int mi = 0; mi < 4; mi++)
            #pragma unroll
            for (int ni = 0; ni < 4; ni++) {
                mma16816(d[mi][ni], afh[mi], bfh[ni]);
                mma16816(d[mi][ni], afh[mi], bfl[ni]);
                mma16816(d[mi][ni], afl[mi], bfh[ni]);
            }
        __syncthreads();
    }

    #pragma unroll
    for (int ni = 0; ni < 4; ni++) {
        const int n = tn * 128 + wn * 32 + ni * 8 + lt * 2;
        const float2 bv = make_float2(__ldg(bi + n) + __ldg(bh + n),
                                      __ldg(bi + n + 1) + __ldg(bh + n + 1));
        #pragma unroll
        for (int mi = 0; mi < 4; mi++) {
            const int m = tm * 128 + wm * 64 + mi * 16 + lg;
            *(float2*)(C + (size_t)m * HDIM + n) =
                make_float2(d[mi][ni][0] + bv.x, d[mi][ni][1] + bv.y);
            *(float2*)(C + (size_t)(m + 8) * HDIM + n) =
                make_float2(d[mi][ni][2] + bv.x, d[mi][ni][3] + bv.y);
        }
    }
}

// ============================================================================
// Recurrent scan — per-peer parallel dataflow, NO trailing barrier.
// 128 CTAs x 256 thr, CTA tile [16b x 32o]. Publish = one contiguous block
// g_Hp2[t&1][cta] = [16b x (32hi|32lo|8pad)] (2304B, row stride 144B).
// Step start: warp0 lane j spin-polls peer j's flag, issues its TMA bulk when
// ready (31 bulks, own block written to smem directly by epilogue). One
// mbarrier, expect_tx 31*2304. Parity ring + entry poll make a trailing
// barrier unnecessary (max lead = 1 step).
// ============================================================================
#define SM_SH   0                              // sH: 32 blocks x 1152 halves (73728 B)
#define SM_RED  73728                          // red f32[8][512] (16384 B)
#define SM_MB   (73728 + 16384)                // mbarrier
#define SCAN_SMEM_BYTES (73728 + 16384 + 16)   // 90,128 B

__global__ void __launch_bounds__(256, 1) scan_kernel(
    const float* __restrict__ P, float* __restrict__ S,
    const float* __restrict__ Whh)
{
    extern __shared__ __align__(16) char smx[];
    uint16_t* sH  = (uint16_t*)(smx + SM_SH);
    float*    red = (float*)(smx + SM_RED);
    const uint32_t mb   = smem_u32(smx + SM_MB);
    const uint32_t sH_a = smem_u32(sH);

    const int tid  = threadIdx.x;
    const int cta  = blockIdx.x;
    const int gbase = cta & ~31;
    const int own  = cta & 31;           // our o-block (peer id in group)
    const int b0 = (cta >> 5) * 16;
    const int o0 = own * 32;
    const int warp = tid >> 5;
    const int lane = tid & 31;
    const int kb = warp * 128;
    const int lg = lane >> 2;
    const int lt = lane & 3;

    // ---- W hi/lo B-fragments in registers (once per layer) ----
    uint32_t bh[4][8][2], bl[4][8][2];
    #pragma unroll
    for (int nt = 0; nt < 4; nt++) {
        const int n = o0 + nt * 8 + lg;
        #pragma unroll
        for (int ks = 0; ks < 8; ks++) {
            const int kk = kb + ks * 16 + lt * 2;
            const float* wr = Whh + (size_t)n * HDIM + kk;
            const float w0 = __ldg(wr),     w1 = __ldg(wr + 1);
            const float w8 = __ldg(wr + 8), w9 = __ldg(wr + 9);
            uint16_t h0, l0, h1, l1, h8, l8, h9, l9;
            bsplit(w0, h0, l0); bsplit(w1, h1, l1);
            bsplit(w8, h8, l8); bsplit(w9, h9, l9);
            bh[nt][ks][0] = pack16(h0, h1); bh[nt][ks][1] = pack16(h8, h9);
            bl[nt][ks][0] = pack16(l0, l1); bl[nt][ks][1] = pack16(l8, l9);
        }
    }

    if (tid == 0) {
        mbar_init(mb, 1);
        fence_proxy_async_shared();
    }

    const unsigned base = g_flags[cta];  // equal across CTAs at launch

    // Epilogue mapping: 2 adjacent outputs per thread
    const int pb = tid >> 4;
    const int po = (tid & 15) * 2;
    const size_t prow = ((size_t)(b0 + pb) * SEQT) * HDIM + o0 + po;
    const int bo = pb * 72 + po;                 // hi offset in block (halves)
    uint16_t* ownB[2] = { (uint16_t*)g_Hp2[0] + (size_t)cta * BLK_H,
                          (uint16_t*)g_Hp2[1] + (size_t)cta * BLK_H };
    uint16_t* sOwn = sH + own * BLK_H;

    // t = 0: h = relu(pre); publish block (slot 0) + own smem block + S
    {
        const float2 p2 = *(const float2*)(P + prow);
        const float h0 = fmaxf(p2.x, 0.f), h1 = fmaxf(p2.y, 0.f);
        *(float2*)(S + prow) = make_float2(h0, h1);
        uint32_t hp, lp; split2(h0, h1, hp, lp);
        *(uint32_t*)(ownB[0] + bo)      = hp;
        *(uint32_t*)(ownB[0] + bo + 32) = lp;
        *(uint32_t*)(sOwn + bo)         = hp;
        *(uint32_t*)(sOwn + bo + 32)    = lp;
    }
    __syncthreads();   // covers mbar_init + own STS + STG before flag
    if (tid == 0) { __threadfence(); g_flags[cta] = base + 1; }

    for (int t = 1; t < SEQT; t++) {
        const float2 p2 = __ldg((const float2*)(P + prow + (size_t)t * HDIM));
        const int sr = (t - 1) & 1;
        const int sw = t & 1;

        // ---- per-peer poll+fetch: warp0 lane j handles peer j ----
        if (warp == 0) {
            if (lane == 0) mbar_expect_tx(mb, 31 * 2304);
            __syncwarp();
            if (lane != own) {
                while (g_flags[gbase + lane] < base + (unsigned)t) { }
                bulk_g2s(sH_a + lane * 2304,
                         (const uint16_t*)g_Hp2[sr] + (size_t)(gbase + lane) * BLK_H,
                         2304, mb);
            }
        }
        mbar_wait(mb, (t - 1) & 1);

        // ---- tensor-core compute: 8 k-steps x 4 n-tiles x 3 combos ----
        float d[4][4];
        #pragma unroll
        for (int nt = 0; nt < 4; nt++)
            #pragma unroll
            for (int r = 0; r < 4; r++) d[nt][r] = 0.f;

        #pragma unroll
        for (int ks = 0; ks < 8; ks++) {
            const int peer = warp * 4 + (ks >> 1);
            const int c = (ks & 1) * 16 + lt * 2;
            const uint16_t* pB = sH + peer * BLK_H + c;
            uint32_t ahi[4], alo[4];
            ahi[0] = *(const uint32_t*)(pB + lg * 72);
            ahi[1] = *(const uint32_t*)(pB + (lg + 8) * 72);
            ahi[2] = *(const uint32_t*)(pB + lg * 72 + 8);
            ahi[3] = *(const uint32_t*)(pB + (lg + 8) * 72 + 8);
            alo[0] = *(const uint32_t*)(pB + lg * 72 + 32);
            alo[1] = *(const uint32_t*)(pB + (lg + 8) * 72 + 32);
            alo[2] = *(const uint32_t*)(pB + lg * 72 + 40);
            alo[3] = *(const uint32_t*)(pB + (lg + 8) * 72 + 40);
            #pragma unroll
            for (int nt = 0; nt < 4; nt++) {
                mma16816(d[nt], ahi, bh[nt][ks]);
                mma16816(d[nt], ahi, bl[nt][ks]);
                mma16816(d[nt], alo, bh[nt][ks]);
            }
        }

        // ---- stash warp partials ----
        #pragma unroll
        for (int nt = 0; nt < 4; nt++) {
            const int oc = nt * 8 + lt * 2;
            *(float2*)&red[warp * 512 + lg * 32 + oc]       = make_float2(d[nt][0], d[nt][1]);
            *(float2*)&red[warp * 512 + (lg + 8) * 32 + oc] = make_float2(d[nt][2], d[nt][3]);
        }
        __syncthreads();   // all MMA reads of sH complete beyond this point

        // ---- final reduce, relu, publish (global block + own smem block) ----
        {
            float s0 = 0.f, s1 = 0.f;
            #pragma unroll
            for (int w8 = 0; w8 < 8; w8++) {
                const float2 v = *(const float2*)&red[w8 * 512 + pb * 32 + po];
                s0 += v.x; s1 += v.y;
            }
            const float h0 = fmaxf(s0 + p2.x, 0.f);
            const float h1 = fmaxf(s1 + p2.y, 0.f);
            *(float2*)(S + prow + (size_t)t * HDIM) = make_float2(h0, h1);
            uint32_t hp, lp; split2(h0, h1, hp, lp);
            *(uint32_t*)(ownB[sw] + bo)      = hp;
            *(uint32_t*)(ownB[sw] + bo + 32) = lp;
            *(uint32_t*)(sOwn + bo)          = hp;
            *(uint32_t*)(sOwn + bo + 32)     = lp;
        }
        __syncthreads();   // STS/STG done before flag + before next TMA issue
        if (tid == 0) { __threadfence(); g_flags[cta] = base + (unsigned)t + 1; }
    }
}

// ============================================================================
// FC: out[64][128] = S[:, T-1, :] @ fc_w^T + fc_b
// ============================================================================
__global__ void __launch_bounds__(128) fc_kernel(
    const float* __restrict__ S, const float* __restrict__ fw,
    const float* __restrict__ fb, float* __restrict__ out)
{
    __shared__ __align__(16) float sx[HDIM];
    const int b = blockIdx.x, tid = threadIdx.x;
    const float* xrow = S + ((size_t)b * SEQT + (SEQT - 1)) * HDIM;
    for (int i = tid; i < HDIM / 4; i += 128)
        *(float4*)&sx[i * 4] = __ldcg((const float4*)(xrow + i * 4));
    __syncthreads();
    float acc = 0.f;
    const float* wrow = fw + (size_t)tid * HDIM;
    #pragma unroll 8
    for (int q = 0; q < HDIM / 4; q++) {
        const float4 w4 = __ldg((const float4*)(wrow + q * 4));
        const float4 x4 = *(const float4*)&sx[q * 4];
        acc += w4.x * x4.x + w4.y * x4.y + w4.z * x4.z + w4.w * x4.w;
    }
    out[(size_t)b * DOUT + tid] = acc + __ldg(fb + tid);
}

// ============================================================================
extern "C" void kernel_launch(void* const* d_in, const int* in_sizes, int n_in,
                              void* d_out, int out_size)
{
    const float* x    = (const float*)d_in[0];   // [64,512,256]
    const float* wih0 = (const float*)d_in[1];   // [1024,256]
    const float* wihr = (const float*)d_in[2];   // [2,1024,1024]
    const float* whh  = (const float*)d_in[3];   // [3,1024,1024]
    const float* bih  = (const float*)d_in[4];   // [3,1024]
    const float* bhh  = (const float*)d_in[5];   // [3,1024]
    const float* fcw  = (const float*)d_in[6];   // [128,1024]
    const float* fcb  = (const float*)d_in[7];   // [128]
    float* out = (float*)d_out;                  // [64,128]

    cudaFuncSetAttribute(scan_kernel, cudaFuncAttributeMaxDynamicSharedMemorySize,
                         SCAN_SMEM_BYTES);

    void *pP = nullptr, *pS = nullptr;
    cudaGetSymbolAddress(&pP, g_P);
    cudaGetSymbolAddress(&pS, g_S);
    float* P  = (float*)pP;
    float* Sq = (float*)pS;

    proj2_kernel<<<2048, 256>>>(x, wih0, bih, bhh, P, DIN);
    scan_kernel<<<GRID, 256, SCAN_SMEM_BYTES>>>(P, Sq, whh);
    proj2_kernel<<<2048, 256>>>(Sq, wihr, bih + HDIM, bhh + HDIM, P, HDIM);
    scan_kernel<<<GRID, 256, SCAN_SMEM_BYTES>>>(P, Sq, whh + (size_t)HDIM * HDIM);
    proj2_kernel<<<2048, 256>>>(Sq, wihr + (size_t)HDIM * HDIM, bih + 2 * HDIM, bhh + 2 * HDIM, P, HDIM);
    scan_kernel<<<GRID, 256, SCAN_SMEM_BYTES>>>(P, Sq, whh + 2 * (size_t)HDIM * HDIM);
    fc_kernel<<<BATCH, 128>>>(Sq, fcw, fcb, out);
}